// round 11
// baseline (speedup 1.0000x reference)
#include <cuda_runtime.h>
#include <cuda_bf16.h>
#include <math.h>

#define EPS 1e-5f
#define F    128
#define F4   32
#define GMAX 1024

// Scratch (__device__ globals; no allocations allowed)
__device__ float g_s1[GMAX * F];
__device__ float g_s2[GMAX * F];
__device__ float g_cnt[GMAX];
__device__ float g_a[GMAX * F];   // rstd * gamma
__device__ float g_b[GMAX * F];   // beta - mean * rstd * gamma

// ---------------------------------------------------------------------------
// 0) zero the accumulators (graph replays -> must run every launch)
// ---------------------------------------------------------------------------
__global__ void zero_kernel() {
    int total = 2 * GMAX * F + GMAX;
    for (int i = blockIdx.x * blockDim.x + threadIdx.x; i < total;
         i += gridDim.x * blockDim.x) {
        if (i < GMAX * F)            g_s1[i] = 0.f;
        else if (i < 2 * GMAX * F)   g_s2[i - GMAX * F] = 0.f;
        else                         g_cnt[i - 2 * GMAX * F] = 0.f;
    }
}

// ---------------------------------------------------------------------------
// 1) per-segment sum/sumsq with float4 loads. batch sorted -> register
//    accumulation, flush on segment change. 512 threads = 16 row lanes x
//    32 feature-groups (float4). 8 row-groups prefetched per iteration.
// ---------------------------------------------------------------------------
__global__ void __launch_bounds__(512) stats_kernel(
    const float4* __restrict__ x4, const int* __restrict__ batch,
    int N, int rows_per_block)
{
    const int f4 = threadIdx.x & 31;    // float4 feature group 0..31
    const int rl = threadIdx.x >> 5;    // row lane 0..15

    const int row0    = blockIdx.x * rows_per_block;
    const int row_end = min(N, row0 + rows_per_block);
    if (row0 >= N) return;

    float4 s1 = {0.f,0.f,0.f,0.f}, s2 = {0.f,0.f,0.f,0.f};
    float  cnt = 0.f;
    int cur = -1;

#define GN_FLUSH()                                                       \
    do {                                                                 \
        if (cur >= 0) {                                                  \
            float* p1 = &g_s1[cur * F + 4 * f4];                         \
            float* p2 = &g_s2[cur * F + 4 * f4];                         \
            atomicAdd(p1 + 0, s1.x); atomicAdd(p1 + 1, s1.y);            \
            atomicAdd(p1 + 2, s1.z); atomicAdd(p1 + 3, s1.w);            \
            atomicAdd(p2 + 0, s2.x); atomicAdd(p2 + 1, s2.y);            \
            atomicAdd(p2 + 2, s2.z); atomicAdd(p2 + 3, s2.w);            \
            if (f4 == 0) atomicAdd(&g_cnt[cur], cnt);                    \
        }                                                                \
    } while (0)

#define GN_PROC(SEG, V)                                                  \
    do {                                                                 \
        if ((SEG) != cur) {                                              \
            GN_FLUSH();                                                  \
            cur = (SEG);                                                 \
            s1.x=0.f;s1.y=0.f;s1.z=0.f;s1.w=0.f;                         \
            s2.x=0.f;s2.y=0.f;s2.z=0.f;s2.w=0.f; cnt = 0.f;              \
        }                                                                \
        s1.x += (V).x; s1.y += (V).y; s1.z += (V).z; s1.w += (V).w;      \
        s2.x += (V).x*(V).x; s2.y += (V).y*(V).y;                        \
        s2.z += (V).z*(V).z; s2.w += (V).w*(V).w;                        \
        cnt += 1.f;                                                      \
    } while (0)

    int r = row0 + rl;
    for (; r + 7 * 16 < row_end; r += 8 * 16) {
        int    sg[8];
        float4 vv[8];
#pragma unroll
        for (int k = 0; k < 8; k++) sg[k] = __ldg(&batch[r + 16 * k]);
#pragma unroll
        for (int k = 0; k < 8; k++) vv[k] = __ldcs(&x4[(size_t)(r + 16 * k) * F4 + f4]);
#pragma unroll
        for (int k = 0; k < 8; k++) GN_PROC(sg[k], vv[k]);
    }
    for (; r < row_end; r += 16) {
        const int    seg = __ldg(&batch[r]);
        const float4 v   = __ldcs(&x4[(size_t)r * F4 + f4]);
        GN_PROC(seg, v);
    }
    GN_FLUSH();
#undef GN_PROC
#undef GN_FLUSH
}

// ---------------------------------------------------------------------------
// 2) finalize into fused affine tables: a = rstd*gamma, b = beta - mean*a
// ---------------------------------------------------------------------------
__global__ void finalize_kernel(const float* __restrict__ gamma,
                                const float* __restrict__ beta) {
    int idx = blockIdx.x * blockDim.x + threadIdx.x;
    if (idx >= GMAX * F) return;
    const int g = idx >> 7;
    const int f = idx & (F - 1);
    const float cntv  = g_cnt[g];
    const float denom = fmaxf(cntv, 1.f);
    const float mean  = g_s1[idx] / denom;
    float var = g_s2[idx] / denom - mean * mean;
    var = fmaxf(var, EPS);
    const float rstd = rsqrtf(var + EPS);
    const float a = rstd * __ldg(&gamma[f]);
    g_a[idx] = a;
    g_b[idx] = __ldg(&beta[f]) - mean * a;
}

// ---------------------------------------------------------------------------
// 3) normalize: grid-stride (stride ≡ 0 mod 32 -> float4 column invariant),
//    8-deep front-batched unroll, 2 L2 table loads + 1 FMA4 per element.
// ---------------------------------------------------------------------------
__global__ void __launch_bounds__(256) norm_kernel(
    const float4* __restrict__ x4, const int* __restrict__ batch,
    float4* __restrict__ out4, int total4)
{
    const float4* __restrict__ a4 = (const float4*)g_a;
    const float4* __restrict__ b4 = (const float4*)g_b;

    const int stride = gridDim.x * blockDim.x;     // 4736*256: % 32 == 0
    const int c      = threadIdx.x & 31;           // invariant float4 column
    int i = blockIdx.x * blockDim.x + threadIdx.x;

    for (; i + 7 * stride < total4; i += 8 * stride) {
        int    sg[8];
        float4 v[8];
#pragma unroll
        for (int k = 0; k < 8; k++) sg[k] = __ldg(&batch[(i + k * stride) >> 5]);
#pragma unroll
        for (int k = 0; k < 8; k++) v[k] = __ldcs(&x4[i + k * stride]);
#pragma unroll
        for (int k = 0; k < 8; k++) {
            const float4 a = __ldg(&a4[sg[k] * F4 + c]);
            const float4 b = __ldg(&b4[sg[k] * F4 + c]);
            float4 o;
            o.x = v[k].x * a.x + b.x;
            o.y = v[k].y * a.y + b.y;
            o.z = v[k].z * a.z + b.z;
            o.w = v[k].w * a.w + b.w;
            __stcs(&out4[i + k * stride], o);
        }
    }
    for (; i < total4; i += stride) {
        const int seg = __ldg(&batch[i >> 5]);
        const float4 v = __ldcs(&x4[i]);
        const float4 a = __ldg(&a4[seg * F4 + c]);
        const float4 b = __ldg(&b4[seg * F4 + c]);
        float4 o;
        o.x = v.x * a.x + b.x;
        o.y = v.y * a.y + b.y;
        o.z = v.z * a.z + b.z;
        o.w = v.w * a.w + b.w;
        __stcs(&out4[i], o);
    }
}

// ---------------------------------------------------------------------------
extern "C" void kernel_launch(void* const* d_in, const int* in_sizes, int n_in,
                              void* d_out, int out_size)
{
    const float* x     = (const float*)d_in[0];
    const float* gamma = (const float*)d_in[1];
    const float* beta  = (const float*)d_in[2];
    const int*   batch = (const int*)d_in[3];

    const int N = in_sizes[3];

    zero_kernel<<<256, 256>>>();

    const int stat_blocks = 2368;       // 148 SMs * 16
    const int stat_rpb = (N + stat_blocks - 1) / stat_blocks;
    stats_kernel<<<stat_blocks, 512>>>((const float4*)x, batch, N, stat_rpb);

    finalize_kernel<<<(GMAX * F + 255) / 256, 256>>>(gamma, beta);

    const int total4 = N * F4;
    const int norm_blocks = 4736;       // 148 SMs * 32
    norm_kernel<<<norm_blocks, 256>>>((const float4*)x, batch,
                                      (float4*)d_out, total4);
}

// round 12
// speedup vs baseline: 1.2200x; 1.2200x over previous
#include <cuda_runtime.h>
#include <cuda_bf16.h>
#include <math.h>

#define EPS 1e-5f

static const int F = 128;        // features (x is [N,128])
static const int F4 = 32;        // float4 per row
static const int GMAX = 1024;    // >= actual batch_size (256)

// Scratch (no allocations allowed): __device__ globals.
__device__ float g_s1[GMAX * F];
__device__ float g_s2[GMAX * F];
__device__ float g_cnt[GMAX];
__device__ float g_a[GMAX * F];   // rstd * gamma
__device__ float g_b[GMAX * F];   // beta - mean * rstd * gamma

// ---------------------------------------------------------------------------
// 0) zero the accumulators
// ---------------------------------------------------------------------------
__global__ void zero_kernel() {
    int total = 2 * GMAX * F + GMAX;
    for (int i = blockIdx.x * blockDim.x + threadIdx.x; i < total;
         i += gridDim.x * blockDim.x) {
        if (i < GMAX * F)            g_s1[i] = 0.f;
        else if (i < 2 * GMAX * F)   g_s2[i - GMAX * F] = 0.f;
        else                         g_cnt[i - 2 * GMAX * F] = 0.f;
    }
}

// ---------------------------------------------------------------------------
// 1) per-segment sum/sumsq (R5 version, proven ~158us). batch sorted ->
//    register accumulation, flush on segment change. 512 threads =
//    4 row lanes x 128 features; 8 row-groups prefetched per iteration.
// ---------------------------------------------------------------------------
__global__ void __launch_bounds__(512) stats_kernel(
    const float* __restrict__ x, const int* __restrict__ batch,
    int N, int rows_per_block)
{
    const int f  = threadIdx.x & (F - 1);
    const int rl = threadIdx.x >> 7;

    const int row0    = blockIdx.x * rows_per_block;
    const int row_end = min(N, row0 + rows_per_block);
    if (row0 >= N) return;

    float s1 = 0.f, s2 = 0.f, cnt = 0.f;
    int cur = -1;

#define GN_FLUSH()                                                      \
    do {                                                                \
        if (cur >= 0) {                                                 \
            atomicAdd(&g_s1[cur * F + f], s1);                          \
            atomicAdd(&g_s2[cur * F + f], s2);                          \
            if (f == 0) atomicAdd(&g_cnt[cur], cnt);                    \
        }                                                               \
    } while (0)

#define GN_PROC(SEG, V)                                                 \
    do {                                                                \
        if ((SEG) != cur) {                                             \
            GN_FLUSH();                                                 \
            cur = (SEG); s1 = 0.f; s2 = 0.f; cnt = 0.f;                 \
        }                                                               \
        s1 += (V); s2 += (V) * (V); cnt += 1.f;                         \
    } while (0)

    int r = row0 + rl;
    for (; r + 28 < row_end; r += 32) {
        int   sg[8];
        float vv[8];
#pragma unroll
        for (int k = 0; k < 8; k++) sg[k] = __ldg(&batch[r + 4 * k]);
#pragma unroll
        for (int k = 0; k < 8; k++) vv[k] = __ldcs(&x[(size_t)(r + 4 * k) * F + f]);
#pragma unroll
        for (int k = 0; k < 8; k++) GN_PROC(sg[k], vv[k]);
    }
    for (; r < row_end; r += 4) {
        const int   seg = __ldg(&batch[r]);
        const float v   = __ldcs(&x[(size_t)r * F + f]);
        GN_PROC(seg, v);
    }
    GN_FLUSH();
#undef GN_PROC
#undef GN_FLUSH
}

// ---------------------------------------------------------------------------
// 2) finalize into fused affine tables: a = rstd*gamma, b = beta - mean*a
// ---------------------------------------------------------------------------
__global__ void finalize_kernel(const float* __restrict__ gamma,
                                const float* __restrict__ beta) {
    int idx = blockIdx.x * blockDim.x + threadIdx.x;
    if (idx >= GMAX * F) return;
    const int g = idx >> 7;
    const int f = idx & (F - 1);
    const float cntv  = g_cnt[g];
    const float denom = fmaxf(cntv, 1.f);
    const float mean  = g_s1[idx] / denom;
    float var = g_s2[idx] / denom - mean * mean;
    var = fmaxf(var, EPS);
    const float rstd = rsqrtf(var + EPS);
    const float a = rstd * __ldg(&gamma[f]);
    g_a[idx] = a;
    g_b[idx] = __ldg(&beta[f]) - mean * a;
}

// ---------------------------------------------------------------------------
// 3) normalize (R5 structure: 4x strided unroll, front-batched loads), but
//    with fused a/b tables: 2 table loads + 1 FMA4 per element, no gamma/beta.
// ---------------------------------------------------------------------------
__global__ void __launch_bounds__(256) norm_kernel(
    const float4* __restrict__ x4, const int* __restrict__ batch,
    float4* __restrict__ out4, int total4)
{
    const float4* __restrict__ a4 = (const float4*)g_a;
    const float4* __restrict__ b4 = (const float4*)g_b;

    const int stride = gridDim.x * blockDim.x;   // 4736*256 ≡ 0 mod 32
    const int c      = threadIdx.x & 31;         // invariant float4 column
    int i = blockIdx.x * blockDim.x + threadIdx.x;

    for (; i + 3 * stride < total4; i += 4 * stride) {
        const int iA = i, iB = i + stride, iC = i + 2 * stride, iD = i + 3 * stride;
        const int sA = __ldg(&batch[iA >> 5]);
        const int sB = __ldg(&batch[iB >> 5]);
        const int sC = __ldg(&batch[iC >> 5]);
        const int sD = __ldg(&batch[iD >> 5]);
        const float4 vA = __ldcs(&x4[iA]);
        const float4 vB = __ldcs(&x4[iB]);
        const float4 vC = __ldcs(&x4[iC]);
        const float4 vD = __ldcs(&x4[iD]);
        const float4 aA = __ldg(&a4[sA * F4 + c]);
        const float4 aB = __ldg(&a4[sB * F4 + c]);
        const float4 aC = __ldg(&a4[sC * F4 + c]);
        const float4 aD = __ldg(&a4[sD * F4 + c]);
        const float4 bA = __ldg(&b4[sA * F4 + c]);
        const float4 bB = __ldg(&b4[sB * F4 + c]);
        const float4 bC = __ldg(&b4[sC * F4 + c]);
        const float4 bD = __ldg(&b4[sD * F4 + c]);
        float4 o;
        o.x = vA.x * aA.x + bA.x;
        o.y = vA.y * aA.y + bA.y;
        o.z = vA.z * aA.z + bA.z;
        o.w = vA.w * aA.w + bA.w;
        __stcs(&out4[iA], o);
        o.x = vB.x * aB.x + bB.x;
        o.y = vB.y * aB.y + bB.y;
        o.z = vB.z * aB.z + bB.z;
        o.w = vB.w * aB.w + bB.w;
        __stcs(&out4[iB], o);
        o.x = vC.x * aC.x + bC.x;
        o.y = vC.y * aC.y + bC.y;
        o.z = vC.z * aC.z + bC.z;
        o.w = vC.w * aC.w + bC.w;
        __stcs(&out4[iC], o);
        o.x = vD.x * aD.x + bD.x;
        o.y = vD.y * aD.y + bD.y;
        o.z = vD.z * aD.z + bD.z;
        o.w = vD.w * aD.w + bD.w;
        __stcs(&out4[iD], o);
    }
    for (; i < total4; i += stride) {
        const int seg = __ldg(&batch[i >> 5]);
        const float4 v = __ldcs(&x4[i]);
        const float4 a = __ldg(&a4[seg * F4 + c]);
        const float4 b = __ldg(&b4[seg * F4 + c]);
        float4 o;
        o.x = v.x * a.x + b.x;
        o.y = v.y * a.y + b.y;
        o.z = v.z * a.z + b.z;
        o.w = v.w * a.w + b.w;
        __stcs(&out4[i], o);
    }
}

// ---------------------------------------------------------------------------
extern "C" void kernel_launch(void* const* d_in, const int* in_sizes, int n_in,
                              void* d_out, int out_size)
{
    const float* x     = (const float*)d_in[0];
    const float* gamma = (const float*)d_in[1];
    const float* beta  = (const float*)d_in[2];
    const int*   batch = (const int*)d_in[3];

    const int N = in_sizes[3];

    zero_kernel<<<256, 256>>>();

    const int stat_blocks = 2368;       // 148 SMs * 16
    const int stat_rpb = (N + stat_blocks - 1) / stat_blocks;
    stats_kernel<<<stat_blocks, 512>>>(x, batch, N, stat_rpb);

    finalize_kernel<<<(GMAX * F + 255) / 256, 256>>>(gamma, beta);

    const int total4 = N * F4;
    const int norm_blocks = 4736;       // 148 SMs * 32
    norm_kernel<<<norm_blocks, 256>>>((const float4*)x, batch,
                                      (float4*)d_out, total4);
}